// round 1
// baseline (speedup 1.0000x reference)
#include <cuda_runtime.h>
#include <math.h>

#define M_ 1024
#define N_ 1024
#define D_ 2048

// ---------------- scratch (static device globals; no runtime alloc) ----------------
__device__ float g_vp[M_ * D_];   // u_p * w3
__device__ float g_rp[M_];        // u_p @ w1
__device__ float g_rc[N_];        // u_c @ w2
__device__ float g_S [M_ * N_];   // scores
__device__ float g_Sa[M_ * N_];   // row softmax
__device__ float g_Sb[M_ * N_];   // col softmax (same layout: g_Sb[j*N + i] normalized over j)
__device__ float g_aa[N_ * D_];   // a_alpha
__device__ float g_ab[N_ * D_];   // a_beta
__device__ float g_part[N_];      // per-row FFN partials

// ---------------- helpers ----------------
__device__ __forceinline__ float block_reduce_sum_256(float v, float* red) {
    int t = threadIdx.x;
    red[t] = v;
    __syncthreads();
    #pragma unroll
    for (int s = 128; s > 0; s >>= 1) {
        if (t < s) red[t] += red[t + s];
        __syncthreads();
    }
    return red[0];
}

// ---------------- K0: r_p, r_c, v_p ----------------
__global__ void rv_kernel(const float* __restrict__ up, const float* __restrict__ uc,
                          const float* __restrict__ wa) {
    __shared__ float red[256];
    int row = blockIdx.x;
    int t = threadIdx.x;
    if (row < M_) {
        const float* a  = up + (size_t)row * D_;
        const float* w1 = wa;
        const float* w3 = wa + 2 * D_;
        float s = 0.f;
        for (int k = t * 4; k < D_; k += 256 * 4) {
            float4 av  = *(const float4*)(a  + k);
            float4 w1v = *(const float4*)(w1 + k);
            float4 w3v = *(const float4*)(w3 + k);
            s += av.x * w1v.x + av.y * w1v.y + av.z * w1v.z + av.w * w1v.w;
            float4 vv = make_float4(av.x * w3v.x, av.y * w3v.y, av.z * w3v.z, av.w * w3v.w);
            *(float4*)(g_vp + (size_t)row * D_ + k) = vv;
        }
        float tot = block_reduce_sum_256(s, red);
        if (t == 0) g_rp[row] = tot;
    } else {
        int r2 = row - M_;
        const float* a  = uc + (size_t)r2 * D_;
        const float* w2 = wa + D_;
        float s = 0.f;
        for (int k = t * 4; k < D_; k += 256 * 4) {
            float4 av  = *(const float4*)(a  + k);
            float4 w2v = *(const float4*)(w2 + k);
            s += av.x * w2v.x + av.y * w2v.y + av.z * w2v.z + av.w * w2v.w;
        }
        float tot = block_reduce_sum_256(s, red);
        if (t == 0) g_rc[r2] = tot;
    }
}

// ---------------- generic tiled SGEMM ----------------
// C[i,j] = sum_k A(i,k) * B(k,j)  (+ optional rank-1 bias rows/cols)
// AKC: A stored k-contiguous (A[i*lda + k]); else A[k*lda + i]
// BJC: B stored j-contiguous (B[k*ldb + j]); else B[j*ldb + k]
template<int BM, int BN, int BK, int TM, int TN, bool AKC, bool BJC, bool BIAS>
__global__ __launch_bounds__(256) void sgemm(
    const float* __restrict__ A, int lda,
    const float* __restrict__ B, int ldb,
    float* __restrict__ C, int ldc,
    int Kdim,
    const float* __restrict__ biasR, const float* __restrict__ biasC)
{
    __shared__ float As[BK][BM];
    __shared__ float Bs[BK][BN];
    const int tid = threadIdx.x;                 // 256 threads
    const int i0 = blockIdx.y * BM;
    const int j0 = blockIdx.x * BN;
    const int trow = tid / (BN / TN);            // 0 .. BM/TM-1
    const int tcol = tid % (BN / TN);            // 0 .. BN/TN-1

    float acc[TM][TN];
    #pragma unroll
    for (int r = 0; r < TM; r++)
        #pragma unroll
        for (int c = 0; c < TN; c++) acc[r][c] = 0.f;

    for (int k0 = 0; k0 < Kdim; k0 += BK) {
        // ---- load A tile ----
        if (AKC) {
            constexpr int V = BK / 4;
            #pragma unroll
            for (int idx = tid; idx < BM * V; idx += 256) {
                int r = idx / V, kq = (idx % V) * 4;
                float4 v = *(const float4*)(A + (size_t)(i0 + r) * lda + k0 + kq);
                As[kq + 0][r] = v.x; As[kq + 1][r] = v.y;
                As[kq + 2][r] = v.z; As[kq + 3][r] = v.w;
            }
        } else {
            constexpr int V = BM / 4;
            #pragma unroll
            for (int idx = tid; idx < BK * V; idx += 256) {
                int kk = idx / V, iq = (idx % V) * 4;
                float4 v = *(const float4*)(A + (size_t)(k0 + kk) * lda + i0 + iq);
                *(float4*)&As[kk][iq] = v;
            }
        }
        // ---- load B tile ----
        if (BJC) {
            constexpr int V = BN / 4;
            #pragma unroll
            for (int idx = tid; idx < BK * V; idx += 256) {
                int kk = idx / V, jq = (idx % V) * 4;
                float4 v = *(const float4*)(B + (size_t)(k0 + kk) * ldb + j0 + jq);
                *(float4*)&Bs[kk][jq] = v;
            }
        } else {
            constexpr int V = BK / 4;
            #pragma unroll
            for (int idx = tid; idx < BN * V; idx += 256) {
                int r = idx / V, kq = (idx % V) * 4;
                float4 v = *(const float4*)(B + (size_t)(j0 + r) * ldb + k0 + kq);
                Bs[kq + 0][r] = v.x; Bs[kq + 1][r] = v.y;
                Bs[kq + 2][r] = v.z; Bs[kq + 3][r] = v.w;
            }
        }
        __syncthreads();
        // ---- compute ----
        #pragma unroll
        for (int kk = 0; kk < BK; kk++) {
            float a[TM], b[TN];
            #pragma unroll
            for (int r = 0; r < TM; r++) a[r] = As[kk][trow * TM + r];
            #pragma unroll
            for (int c = 0; c < TN; c++) b[c] = Bs[kk][tcol * TN + c];
            #pragma unroll
            for (int r = 0; r < TM; r++)
                #pragma unroll
                for (int c = 0; c < TN; c++) acc[r][c] += a[r] * b[c];
        }
        __syncthreads();
    }
    // ---- epilogue ----
    #pragma unroll
    for (int r = 0; r < TM; r++) {
        int gi = i0 + trow * TM + r;
        #pragma unroll
        for (int c = 0; c < TN; c++) {
            int gj = j0 + tcol * TN + c;
            float v = acc[r][c];
            if (BIAS) v += biasR[gi] + biasC[gj];
            C[(size_t)gi * ldc + gj] = v;
        }
    }
}

// ---------------- K2: row softmax ----------------
__global__ void row_softmax(const float* __restrict__ S, float* __restrict__ out) {
    __shared__ float red[256];
    int row = blockIdx.x, t = threadIdx.x;
    const float4* p = (const float4*)(S + (size_t)row * N_);
    float4 v = p[t];                       // 256 threads * 4 = 1024
    float mx = fmaxf(fmaxf(v.x, v.y), fmaxf(v.z, v.w));
    red[t] = mx;
    __syncthreads();
    #pragma unroll
    for (int s = 128; s > 0; s >>= 1) {
        if (t < s) red[t] = fmaxf(red[t], red[t + s]);
        __syncthreads();
    }
    mx = red[0];
    __syncthreads();
    float e0 = __expf(v.x - mx), e1 = __expf(v.y - mx);
    float e2 = __expf(v.z - mx), e3 = __expf(v.w - mx);
    float sum = block_reduce_sum_256(e0 + e1 + e2 + e3, red);
    float inv = 1.0f / sum;
    float4 o = make_float4(e0 * inv, e1 * inv, e2 * inv, e3 * inv);
    ((float4*)(out + (size_t)row * N_))[t] = o;
}

// ---------------- K3: column softmax (online) ----------------
__global__ void col_softmax(const float* __restrict__ S, float* __restrict__ out) {
    __shared__ float sm_m[8][32];
    __shared__ float sm_s[8][32];
    int tx = threadIdx.x;                  // 32 columns per block
    int ty = threadIdx.y;                  // 8 row-strides
    int c = blockIdx.x * 32 + tx;
    float mx = -INFINITY, sm = 0.f;
    for (int r = ty; r < M_; r += 8) {
        float v = S[(size_t)r * N_ + c];
        float mn = fmaxf(mx, v);
        sm = sm * __expf(mx - mn) + __expf(v - mn);
        mx = mn;
    }
    sm_m[ty][tx] = mx; sm_s[ty][tx] = sm;
    __syncthreads();
    if (ty == 0) {
        float m = sm_m[0][tx], s = sm_s[0][tx];
        #pragma unroll
        for (int k = 1; k < 8; k++) {
            float m2 = sm_m[k][tx], s2 = sm_s[k][tx];
            float mn = fmaxf(m, m2);
            s = s * __expf(m - mn) + s2 * __expf(m2 - mn);
            m = mn;
        }
        sm_m[0][tx] = m;
        sm_s[0][tx] = 1.0f / s;
    }
    __syncthreads();
    float Mv = sm_m[0][tx], inv = sm_s[0][tx];
    for (int r = ty; r < M_; r += 8) {
        float v = S[(size_t)r * N_ + c];
        out[(size_t)r * N_ + c] = __expf(v - Mv) * inv;
    }
}

// ---------------- K6: FFN partial dot per row ----------------
__global__ void ffn_partial(const float* __restrict__ up, const float* __restrict__ uc,
                            const float* __restrict__ W) {
    __shared__ float red[256];
    int i = blockIdx.x, t = threadIdx.x;
    const float* Wi = W + (size_t)i * 4 * D_;
    const float* upi = up + (size_t)i * D_;
    const float* uci = uc + (size_t)i * D_;
    const float* aai = g_aa + (size_t)i * D_;
    const float* abi = g_ab + (size_t)i * D_;
    float s = 0.f;
    for (int k = t * 4; k < D_; k += 256 * 4) {
        float4 u  = *(const float4*)(upi + k);
        float4 aa = *(const float4*)(aai + k);
        float4 ab = *(const float4*)(abi + k);
        float4 cc = *(const float4*)(uci + k);
        float4 w0 = *(const float4*)(Wi + k);
        float4 w1 = *(const float4*)(Wi + D_ + k);
        float4 w2 = *(const float4*)(Wi + 2 * D_ + k);
        float4 w3 = *(const float4*)(Wi + 3 * D_ + k);
        s += u.x * w0.x + u.y * w0.y + u.z * w0.z + u.w * w0.w;
        s += aa.x * w1.x + aa.y * w1.y + aa.z * w1.z + aa.w * w1.w;
        s += u.x * aa.x * w2.x + u.y * aa.y * w2.y + u.z * aa.z * w2.z + u.w * aa.w * w2.w;
        s += cc.x * ab.x * w3.x + cc.y * ab.y * w3.y + cc.z * ab.z * w3.z + cc.w * ab.w * w3.w;
    }
    float tot = block_reduce_sum_256(s, red);
    if (t == 0) g_part[i] = tot;
}

// ---------------- K7: final scalar ----------------
__global__ void ffn_final(const float* __restrict__ b, float* __restrict__ out) {
    __shared__ float red[256];
    int t = threadIdx.x;
    float s = 0.f;
    for (int i = t; i < N_; i += 256) s += g_part[i];
    float tot = block_reduce_sum_256(s, red);
    if (t == 0) out[0] = fmaxf(tot + b[0], 0.f);
}

// ---------------- launch ----------------
extern "C" void kernel_launch(void* const* d_in, const int* in_sizes, int n_in,
                              void* d_out, int out_size) {
    const float* u_p   = (const float*)d_in[0];
    const float* u_c   = (const float*)d_in[1];
    const float* w_a   = (const float*)d_in[2];
    const float* ffn_w = (const float*)d_in[3];
    const float* ffn_b = (const float*)d_in[4];
    float* out = (float*)d_out;

    float *vp, *rp, *rc, *S, *Sa, *Sb, *aa, *ab;
    cudaGetSymbolAddress((void**)&vp, g_vp);
    cudaGetSymbolAddress((void**)&rp, g_rp);
    cudaGetSymbolAddress((void**)&rc, g_rc);
    cudaGetSymbolAddress((void**)&S,  g_S);
    cudaGetSymbolAddress((void**)&Sa, g_Sa);
    cudaGetSymbolAddress((void**)&Sb, g_Sb);
    cudaGetSymbolAddress((void**)&aa, g_aa);
    cudaGetSymbolAddress((void**)&ab, g_ab);

    // K0: r_p, r_c, v_p
    rv_kernel<<<M_ + N_, 256>>>(u_p, u_c, w_a);

    // K1: S = v_p @ u_c^T + r_p + r_c   (NT)
    sgemm<128, 64, 16, 8, 4, true, false, true>
        <<<dim3(N_ / 64, M_ / 128), 256>>>(vp, D_, u_c, D_, S, N_, D_, rp, rc);

    // K2/K3: softmaxes
    row_softmax<<<M_, 256>>>(S, Sa);
    col_softmax<<<N_ / 32, dim3(32, 8)>>>(S, Sb);

    // K4: a_alpha = S_alpha @ u_c   (NN)
    sgemm<128, 64, 16, 8, 4, true, true, false>
        <<<dim3(D_ / 64, N_ / 128), 256>>>(Sa, N_, u_c, D_, aa, D_, M_, nullptr, nullptr);

    // K5: a_beta = S_beta^T @ u_p   (TN; A = g_Sb with i contiguous)
    sgemm<128, 64, 16, 8, 4, false, true, false>
        <<<dim3(D_ / 64, N_ / 128), 256>>>(Sb, N_, u_p, D_, ab, D_, M_, nullptr, nullptr);

    // K6/K7: fused FFN dot + relu
    ffn_partial<<<N_, 256>>>(u_p, u_c, ffn_w);
    ffn_final<<<1, 256>>>(ffn_b, out);
}

// round 4
// speedup vs baseline: 2.0642x; 2.0642x over previous
#include <cuda_runtime.h>
#include <cuda_bf16.h>
#include <cstdint>
#include <math.h>

#define M_ 1024
#define N_ 1024
#define D_ 2048

// ================= helpers =================
__device__ __forceinline__ uint32_t smem_to_u32(const void* p) {
    uint32_t a;
    asm("{ .reg .u64 t; cvta.to.shared.u64 t, %1; cvt.u32.u64 %0, t; }" : "=r"(a) : "l"(p));
    return a;
}
#define SMEM_SWIZZLE_128B(b) ((b) ^ (((b) >> 3) & 0x70))

#define LDSM_X4(r, a) \
    asm volatile("ldmatrix.sync.aligned.m8n8.x4.shared.b16 {%0,%1,%2,%3}, [%4];" \
        : "=r"((r)[0]), "=r"((r)[1]), "=r"((r)[2]), "=r"((r)[3]) : "r"(a))

__device__ __forceinline__ void mma16816(float* c, const uint32_t* a, uint32_t b0, uint32_t b1) {
    asm volatile("mma.sync.aligned.m16n8k16.row.col.f32.bf16.bf16.f32 "
        "{%0,%1,%2,%3}, {%4,%5,%6,%7}, {%8,%9}, {%0,%1,%2,%3};"
        : "+f"(c[0]), "+f"(c[1]), "+f"(c[2]), "+f"(c[3])
        : "r"(a[0]), "r"(a[1]), "r"(a[2]), "r"(a[3]), "r"(b0), "r"(b1));
}

// ================= scratch =================
__device__ __nv_bfloat16 g_vph[M_ * D_], g_vpl[M_ * D_];
__device__ __nv_bfloat16 g_uch[N_ * D_], g_ucl[N_ * D_];
__device__ __nv_bfloat16 g_ucTh[D_ * N_], g_ucTl[D_ * N_];
__device__ __nv_bfloat16 g_upTh[D_ * M_], g_upTl[D_ * M_];
__device__ __nv_bfloat16 g_Sah[M_ * N_], g_Sal[M_ * N_];
__device__ __nv_bfloat16 g_SbTh[N_ * M_], g_SbTl[N_ * M_];
__device__ float g_S[M_ * N_];
__device__ float g_rp[M_], g_rc[N_];
__device__ float g_pmax[8 * N_], g_psum[8 * N_];
__device__ float g_cmax[N_], g_cinv[N_];
__device__ float g_aa[N_ * D_], g_ab[N_ * D_];
__device__ float g_part[N_];

__device__ __forceinline__ void split_store(__nv_bfloat16* oh, __nv_bfloat16* ol,
                                            size_t off, float4 v) {
    __nv_bfloat16 h0 = __float2bfloat16(v.x), h1 = __float2bfloat16(v.y);
    __nv_bfloat16 h2 = __float2bfloat16(v.z), h3 = __float2bfloat16(v.w);
    __nv_bfloat16 l0 = __float2bfloat16(v.x - __bfloat162float(h0));
    __nv_bfloat16 l1 = __float2bfloat16(v.y - __bfloat162float(h1));
    __nv_bfloat16 l2 = __float2bfloat16(v.z - __bfloat162float(h2));
    __nv_bfloat16 l3 = __float2bfloat16(v.w - __bfloat162float(h3));
    *(__nv_bfloat162*)(oh + off)     = __halves2bfloat162(h0, h1);
    *(__nv_bfloat162*)(oh + off + 2) = __halves2bfloat162(h2, h3);
    *(__nv_bfloat162*)(ol + off)     = __halves2bfloat162(l0, l1);
    *(__nv_bfloat162*)(ol + off + 2) = __halves2bfloat162(l2, l3);
}

__device__ __forceinline__ float block_reduce_sum_256(float v, float* red) {
    int t = threadIdx.x;
    red[t] = v;
    __syncthreads();
    #pragma unroll
    for (int s = 128; s > 0; s >>= 1) {
        if (t < s) red[t] += red[t + s];
        __syncthreads();
    }
    return red[0];
}

// ================= K0: rp, rc, vp hi/lo, uc hi/lo =================
__global__ void rv_kernel(const float* __restrict__ up, const float* __restrict__ uc,
                          const float* __restrict__ wa) {
    __shared__ float red[256];
    int row = blockIdx.x, t = threadIdx.x;
    if (row < M_) {
        const float* a = up + (size_t)row * D_;
        const float* w1 = wa;
        const float* w3 = wa + 2 * D_;
        float s = 0.f;
        for (int k = t * 4; k < D_; k += 1024) {
            float4 av = *(const float4*)(a + k);
            float4 w1v = *(const float4*)(w1 + k);
            float4 w3v = *(const float4*)(w3 + k);
            s += av.x * w1v.x + av.y * w1v.y + av.z * w1v.z + av.w * w1v.w;
            float4 vv = make_float4(av.x * w3v.x, av.y * w3v.y, av.z * w3v.z, av.w * w3v.w);
            split_store(g_vph, g_vpl, (size_t)row * D_ + k, vv);
        }
        float tot = block_reduce_sum_256(s, red);
        if (t == 0) g_rp[row] = tot;
    } else {
        int r2 = row - M_;
        const float* a = uc + (size_t)r2 * D_;
        const float* w2 = wa + D_;
        float s = 0.f;
        for (int k = t * 4; k < D_; k += 1024) {
            float4 av = *(const float4*)(a + k);
            float4 w2v = *(const float4*)(w2 + k);
            s += av.x * w2v.x + av.y * w2v.y + av.z * w2v.z + av.w * w2v.w;
            split_store(g_uch, g_ucl, (size_t)r2 * D_ + k, av);
        }
        float tot = block_reduce_sum_256(s, red);
        if (t == 0) g_rc[r2] = tot;
    }
}

// ================= transpose + split convert =================
__global__ void transpose_split(const float* __restrict__ in, int R, int C,
                                __nv_bfloat16* __restrict__ oh, __nv_bfloat16* __restrict__ ol) {
    __shared__ float t[32][33];
    int tx = threadIdx.x, ty = threadIdx.y;
    int r0 = blockIdx.y * 32, c0 = blockIdx.x * 32;
    #pragma unroll
    for (int j = 0; j < 4; j++)
        t[ty + j * 8][tx] = in[(size_t)(r0 + ty + j * 8) * C + c0 + tx];
    __syncthreads();
    #pragma unroll
    for (int j = 0; j < 4; j++) {
        int c = c0 + ty + j * 8;
        float v = t[tx][ty + j * 8];
        __nv_bfloat16 h = __float2bfloat16(v);
        __nv_bfloat16 l = __float2bfloat16(v - __bfloat162float(h));
        oh[(size_t)c * R + r0 + tx] = h;
        ol[(size_t)c * R + r0 + tx] = l;
    }
}

__global__ void transpose_softmax_split(const float* __restrict__ S) {
    __shared__ float t[32][33];
    int tx = threadIdx.x, ty = threadIdx.y;
    int r0 = blockIdx.y * 32, c0 = blockIdx.x * 32;
    float cm = g_cmax[c0 + tx], ci = g_cinv[c0 + tx];
    #pragma unroll
    for (int j = 0; j < 4; j++) {
        float v = S[(size_t)(r0 + ty + j * 8) * N_ + c0 + tx];
        t[ty + j * 8][tx] = __expf(v - cm) * ci;
    }
    __syncthreads();
    #pragma unroll
    for (int j = 0; j < 4; j++) {
        int c = c0 + ty + j * 8;
        float v = t[tx][ty + j * 8];
        __nv_bfloat16 h = __float2bfloat16(v);
        __nv_bfloat16 l = __float2bfloat16(v - __bfloat162float(h));
        g_SbTh[(size_t)c * M_ + r0 + tx] = h;
        g_SbTl[(size_t)c * M_ + r0 + tx] = l;
    }
}

// ================= col softmax stats =================
__global__ void col_stats_part(const float* __restrict__ S) {
    int tx = threadIdx.x, ty = threadIdx.y;
    int c = blockIdx.x * 128 + tx;
    int r0 = blockIdx.y * 128;
    float mx = -INFINITY, sm = 0.f;
    for (int r = ty; r < 128; r += 4) {
        float v = S[(size_t)(r0 + r) * N_ + c];
        float mn = fmaxf(mx, v);
        sm = sm * __expf(mx - mn) + __expf(v - mn);
        mx = mn;
    }
    __shared__ float m2[4][128], s2[4][128];
    m2[ty][tx] = mx; s2[ty][tx] = sm;
    __syncthreads();
    if (ty == 0) {
        float m = m2[0][tx], s = s2[0][tx];
        #pragma unroll
        for (int k = 1; k < 4; k++) {
            float mm = m2[k][tx], ss = s2[k][tx];
            float mn = fmaxf(m, mm);
            s = s * __expf(m - mn) + ss * __expf(mm - mn);
            m = mn;
        }
        g_pmax[blockIdx.y * N_ + c] = m;
        g_psum[blockIdx.y * N_ + c] = s;
    }
}

__global__ void col_stats_combine() {
    int c = blockIdx.x * 256 + threadIdx.x;
    float m = g_pmax[c], s = g_psum[c];
    #pragma unroll
    for (int k = 1; k < 8; k++) {
        float mm = g_pmax[k * N_ + c], ss = g_psum[k * N_ + c];
        float mn = fmaxf(m, mm);
        s = s * __expf(m - mn) + ss * __expf(mm - mn);
        m = mn;
    }
    g_cmax[c] = m;
    g_cinv[c] = 1.0f / s;
}

// ================= row softmax -> Sa hi/lo =================
__global__ void row_softmax_split(const float* __restrict__ S) {
    __shared__ float red[256];
    int row = blockIdx.x, t = threadIdx.x;
    float4 v = ((const float4*)(S + (size_t)row * N_))[t];
    float mx = fmaxf(fmaxf(v.x, v.y), fmaxf(v.z, v.w));
    red[t] = mx;
    __syncthreads();
    #pragma unroll
    for (int s = 128; s > 0; s >>= 1) {
        if (t < s) red[t] = fmaxf(red[t], red[t + s]);
        __syncthreads();
    }
    mx = red[0];
    __syncthreads();
    float e0 = __expf(v.x - mx), e1 = __expf(v.y - mx);
    float e2 = __expf(v.z - mx), e3 = __expf(v.w - mx);
    float sum = block_reduce_sum_256(e0 + e1 + e2 + e3, red);
    float inv = 1.0f / sum;
    split_store(g_Sah, g_Sal, (size_t)row * N_ + t * 4,
                make_float4(e0 * inv, e1 * inv, e2 * inv, e3 * inv));
}

// ================= mma.sync GEMM (bf16 hi/lo x3 passes) =================
#define NSTG 3
#define TILE_B 16384
#define SMEM_GEMM (2 * NSTG * TILE_B)

__device__ __forceinline__ void cp_tile(uint32_t sdst, const __nv_bfloat16* src,
                                        int row0, int ld, int k0, int tid) {
    const char* gb = (const char*)(src + (size_t)row0 * ld + k0);
    size_t rb = (size_t)ld * 2;
    #pragma unroll
    for (int it = 0; it < 4; it++) {
        int idx = tid + it * 256;
        int r = idx >> 3;
        int cb = (idx & 7) << 4;
        const void* g = gb + (size_t)r * rb + cb;
        uint32_t s = sdst + SMEM_SWIZZLE_128B(r * 128 + cb);
        asm volatile("cp.async.cg.shared.global [%0], [%1], 16;" :: "r"(s), "l"(g));
    }
}

template<bool BIAS>
__global__ __launch_bounds__(256) void gemm_mma3(
    const __nv_bfloat16* __restrict__ Ahi, const __nv_bfloat16* __restrict__ Alo,
    const __nv_bfloat16* __restrict__ Bhi, const __nv_bfloat16* __restrict__ Blo,
    float* __restrict__ C, int ldc, int Kdim,
    const float* __restrict__ biasR, const float* __restrict__ biasC)
{
    extern __shared__ __align__(1024) char smem[];
    uint32_t sb = smem_to_u32(smem);
    const int tid = threadIdx.x;
    const int wid = tid >> 5, lane = tid & 31;
    const int wm = wid & 1, wn = wid >> 1;      // warp tile 64x32 in 2x4 grid
    const int i0 = blockIdx.y * 128;
    const int j0 = blockIdx.x * 128;

    float acc[4][4][4];
    #pragma unroll
    for (int a = 0; a < 4; a++)
        #pragma unroll
        for (int b = 0; b < 4; b++)
            #pragma unroll
            for (int c = 0; c < 4; c++) acc[a][b][c] = 0.f;

    // per-thread ldmatrix offsets, swizzled once; k-step applied via XOR
    // (ks*32 hits bits 5-6, disjoint from the unswizzled col bits (bit 4),
    //  so swizzle(col + ks*32) == swizzle(col) ^ (ks*32) — no carry, in-bounds)
    uint32_t cA = (uint32_t)((wm * 64 + (lane & 15)) << 7) + ((lane >> 4) << 4);
    cA ^= ((cA >> 3) & 0x70);
    uint32_t rowB = (lane & 7) + ((lane >> 4) << 3);
    uint32_t cB = (uint32_t)((wn * 32 + rowB) << 7) + (((lane >> 3) & 1) << 4);
    cB ^= ((cB >> 3) & 0x70);

    const int nkc = Kdim >> 6;
    const int nch = 3 * nkc;

    #define STG_A(s) (sb + (s) * TILE_B)
    #define STG_B(s) (sb + NSTG * TILE_B + (s) * TILE_B)
    #define CHUNK_SRC(ci) { int p = (ci) / nkc; int kc = (ci) - p * nkc; kk = kc << 6; \
                            As = (p == 1) ? Alo : Ahi; Bs = (p == 2) ? Blo : Bhi; }

    {
        const __nv_bfloat16 *As, *Bs; int kk;
        CHUNK_SRC(0);
        cp_tile(STG_A(0), As, i0, Kdim, kk, tid);
        cp_tile(STG_B(0), Bs, j0, Kdim, kk, tid);
        asm volatile("cp.async.commit_group;" ::: "memory");
        CHUNK_SRC(1);
        cp_tile(STG_A(1), As, i0, Kdim, kk, tid);
        cp_tile(STG_B(1), Bs, j0, Kdim, kk, tid);
        asm volatile("cp.async.commit_group;" ::: "memory");
    }

    for (int i = 0; i < nch; i++) {
        int s = i % NSTG;
        asm volatile("cp.async.wait_group 1;" ::: "memory");
        __syncthreads();
        uint32_t aBase = STG_A(s) + cA;
        uint32_t bBase = STG_B(s) + cB;
        #pragma unroll
        for (int ks = 0; ks < 4; ks++) {
            uint32_t afr[4][4], bfr[2][4];
            #pragma unroll
            for (int mt = 0; mt < 4; mt++)
                LDSM_X4(afr[mt], (aBase + mt * 2048) ^ (ks << 5));
            #pragma unroll
            for (int p = 0; p < 2; p++)
                LDSM_X4(bfr[p], (bBase + p * 2048) ^ (ks << 5));
            #pragma unroll
            for (int mt = 0; mt < 4; mt++) {
                #pragma unroll
                for (int p = 0; p < 2; p++) {
                    mma16816(acc[mt][p * 2 + 0], afr[mt], bfr[p][0], bfr[p][1]);
                    mma16816(acc[mt][p * 2 + 1], afr[mt], bfr[p][2], bfr[p][3]);
                }
            }
        }
        __syncthreads();
        if (i + 2 < nch) {
            const __nv_bfloat16 *As, *Bs; int kk;
            CHUNK_SRC(i + 2);
            cp_tile(STG_A((i + 2) % NSTG), As, i0, Kdim, kk, tid);
            cp_tile(STG_B((i + 2) % NSTG), Bs, j0, Kdim, kk, tid);
        }
        asm volatile("cp.async.commit_group;" ::: "memory");
    }

    const int gid = lane >> 2, tig = lane & 3;
    #pragma unroll
    for (int mt = 0; mt < 4; mt++) {
        int gi = i0 + wm * 64 + mt * 16 + gid;
        float br0 = BIAS ? biasR[gi] : 0.f;
        float br8 = BIAS ? biasR[gi + 8] : 0.f;
        #pragma unroll
        for (int nt = 0; nt < 4; nt++) {
            int gj = j0 + wn * 32 + nt * 8 + tig * 2;
            float bc0 = BIAS ? biasC[gj] : 0.f;
            float bc1 = BIAS ? biasC[gj + 1] : 0.f;
            float2 v0 = make_float2(acc[mt][nt][0] + br0 + bc0, acc[mt][nt][1] + br0 + bc1);
            float2 v1 = make_float2(acc[mt][nt][2] + br8 + bc0, acc[mt][nt][3] + br8 + bc1);
            *(float2*)(C + (size_t)gi * ldc + gj) = v0;
            *(float2*)(C + (size_t)(gi + 8) * ldc + gj) = v1;
        }
    }
}

// ================= FFN =================
__global__ void ffn_partial(const float* __restrict__ up, const float* __restrict__ uc,
                            const float* __restrict__ W) {
    __shared__ float red[256];
    int i = blockIdx.x, t = threadIdx.x;
    const float* Wi = W + (size_t)i * 4 * D_;
    const float* upi = up + (size_t)i * D_;
    const float* uci = uc + (size_t)i * D_;
    const float* aai = g_aa + (size_t)i * D_;
    const float* abi = g_ab + (size_t)i * D_;
    float s = 0.f;
    for (int k = t * 4; k < D_; k += 1024) {
        float4 u  = *(const float4*)(upi + k);
        float4 aa = *(const float4*)(aai + k);
        float4 ab = *(const float4*)(abi + k);
        float4 cc = *(const float4*)(uci + k);
        float4 w0 = *(const float4*)(Wi + k);
        float4 w1 = *(const float4*)(Wi + D_ + k);
        float4 w2 = *(const float4*)(Wi + 2 * D_ + k);
        float4 w3 = *(const float4*)(Wi + 3 * D_ + k);
        s += u.x * w0.x + u.y * w0.y + u.z * w0.z + u.w * w0.w;
        s += aa.x * w1.x + aa.y * w1.y + aa.z * w1.z + aa.w * w1.w;
        s += u.x * aa.x * w2.x + u.y * aa.y * w2.y + u.z * aa.z * w2.z + u.w * aa.w * w2.w;
        s += cc.x * ab.x * w3.x + cc.y * ab.y * w3.y + cc.z * ab.z * w3.z + cc.w * ab.w * w3.w;
    }
    float tot = block_reduce_sum_256(s, red);
    if (t == 0) g_part[i] = tot;
}

__global__ void ffn_final(const float* __restrict__ b, float* __restrict__ out) {
    __shared__ float red[256];
    int t = threadIdx.x;
    float s = 0.f;
    for (int i = t; i < N_; i += 256) s += g_part[i];
    float tot = block_reduce_sum_256(s, red);
    if (t == 0) out[0] = fmaxf(tot + b[0], 0.f);
}

// ================= launch =================
extern "C" void kernel_launch(void* const* d_in, const int* in_sizes, int n_in,
                              void* d_out, int out_size) {
    const float* u_p   = (const float*)d_in[0];
    const float* u_c   = (const float*)d_in[1];
    const float* w_a   = (const float*)d_in[2];
    const float* ffn_w = (const float*)d_in[3];
    const float* ffn_b = (const float*)d_in[4];
    float* out = (float*)d_out;

    cudaFuncSetAttribute(gemm_mma3<true>,  cudaFuncAttributeMaxDynamicSharedMemorySize, SMEM_GEMM);
    cudaFuncSetAttribute(gemm_mma3<false>, cudaFuncAttributeMaxDynamicSharedMemorySize, SMEM_GEMM);

    float *S, *rp, *rc, *aa, *ab;
    __nv_bfloat16 *vph, *vpl, *uch, *ucl, *ucTh, *ucTl, *upTh, *upTl, *Sah, *Sal, *SbTh, *SbTl;
    cudaGetSymbolAddress((void**)&S, g_S);
    cudaGetSymbolAddress((void**)&rp, g_rp);
    cudaGetSymbolAddress((void**)&rc, g_rc);
    cudaGetSymbolAddress((void**)&aa, g_aa);
    cudaGetSymbolAddress((void**)&ab, g_ab);
    cudaGetSymbolAddress((void**)&vph, g_vph);
    cudaGetSymbolAddress((void**)&vpl, g_vpl);
    cudaGetSymbolAddress((void**)&uch, g_uch);
    cudaGetSymbolAddress((void**)&ucl, g_ucl);
    cudaGetSymbolAddress((void**)&ucTh, g_ucTh);
    cudaGetSymbolAddress((void**)&ucTl, g_ucTl);
    cudaGetSymbolAddress((void**)&upTh, g_upTh);
    cudaGetSymbolAddress((void**)&upTl, g_upTl);
    cudaGetSymbolAddress((void**)&Sah, g_Sah);
    cudaGetSymbolAddress((void**)&Sal, g_Sal);
    cudaGetSymbolAddress((void**)&SbTh, g_SbTh);
    cudaGetSymbolAddress((void**)&SbTl, g_SbTl);

    // K0: rp, rc, vp hi/lo, uc hi/lo
    rv_kernel<<<M_ + N_, 256>>>(u_p, u_c, w_a);

    // transposed splits for GEMM2/3 B operands
    transpose_split<<<dim3(D_ / 32, N_ / 32), dim3(32, 8)>>>(u_c, N_, D_, ucTh, ucTl);
    transpose_split<<<dim3(D_ / 32, M_ / 32), dim3(32, 8)>>>(u_p, M_, D_, upTh, upTl);

    // GEMM1: S = vp @ uc^T + rp + rc
    gemm_mma3<true><<<dim3(N_ / 128, M_ / 128), 256, SMEM_GEMM>>>(
        vph, vpl, uch, ucl, S, N_, D_, rp, rc);

    // softmaxes
    row_softmax_split<<<M_, 256>>>(S);
    col_stats_part<<<dim3(N_ / 128, 8), dim3(128, 4)>>>(S);
    col_stats_combine<<<N_ / 256, 256>>>();
    transpose_softmax_split<<<dim3(N_ / 32, M_ / 32), dim3(32, 8)>>>(S);

    // GEMM2: aa = Sa @ uc
    gemm_mma3<false><<<dim3(D_ / 128, M_ / 128), 256, SMEM_GEMM>>>(
        Sah, Sal, ucTh, ucTl, aa, D_, N_, nullptr, nullptr);

    // GEMM3: ab = Sb^T @ up
    gemm_mma3<false><<<dim3(D_ / 128, N_ / 128), 256, SMEM_GEMM>>>(
        SbTh, SbTl, upTh, upTl, ab, D_, M_, nullptr, nullptr);

    // FFN
    ffn_partial<<<N_, 256>>>(u_p, u_c, ffn_w);
    ffn_final<<<1, 256>>>(ffn_b, out);
}

// round 5
// speedup vs baseline: 2.7738x; 1.3438x over previous
#include <cuda_runtime.h>
#include <cuda_bf16.h>
#include <cstdint>
#include <math.h>

#define M_ 1024
#define N_ 1024
#define D_ 2048

// ================= helpers =================
__device__ __forceinline__ uint32_t smem_to_u32(const void* p) {
    uint32_t a;
    asm("{ .reg .u64 t; cvta.to.shared.u64 t, %1; cvt.u32.u64 %0, t; }" : "=r"(a) : "l"(p));
    return a;
}
#define SMEM_SWIZZLE_128B(b) ((b) ^ (((b) >> 3) & 0x70))

#define LDSM_X4(r, a) \
    asm volatile("ldmatrix.sync.aligned.m8n8.x4.shared.b16 {%0,%1,%2,%3}, [%4];" \
        : "=r"((r)[0]), "=r"((r)[1]), "=r"((r)[2]), "=r"((r)[3]) : "r"(a))

__device__ __forceinline__ void mma16816(float* c, const uint32_t* a, uint32_t b0, uint32_t b1) {
    asm volatile("mma.sync.aligned.m16n8k16.row.col.f32.bf16.bf16.f32 "
        "{%0,%1,%2,%3}, {%4,%5,%6,%7}, {%8,%9}, {%0,%1,%2,%3};"
        : "+f"(c[0]), "+f"(c[1]), "+f"(c[2]), "+f"(c[3])
        : "r"(a[0]), "r"(a[1]), "r"(a[2]), "r"(a[3]), "r"(b0), "r"(b1));
}

// ================= scratch =================
__device__ __nv_bfloat16 g_vph[M_ * D_], g_vpl[M_ * D_];
__device__ __nv_bfloat16 g_uch[N_ * D_], g_ucl[N_ * D_];
__device__ __nv_bfloat16 g_ucTh[D_ * N_], g_ucTl[D_ * N_];
__device__ __nv_bfloat16 g_upTh[D_ * M_], g_upTl[D_ * M_];
__device__ __nv_bfloat16 g_Sah[M_ * N_], g_Sal[M_ * N_];
__device__ __nv_bfloat16 g_SbTh[N_ * M_], g_SbTl[N_ * M_];
__device__ float g_Sp[4 * M_ * N_];   // GEMM1 split-K partials
__device__ float g_S[M_ * N_];
__device__ float g_rp[M_], g_rc[N_];
__device__ float g_pmax[8 * N_], g_psum[8 * N_];
__device__ float g_cmax[N_], g_cinv[N_];
__device__ float g_aa[N_ * D_], g_ab[N_ * D_];
__device__ float g_part[N_];

__device__ __forceinline__ void split_store(__nv_bfloat16* oh, __nv_bfloat16* ol,
                                            size_t off, float4 v) {
    __nv_bfloat16 h0 = __float2bfloat16(v.x), h1 = __float2bfloat16(v.y);
    __nv_bfloat16 h2 = __float2bfloat16(v.z), h3 = __float2bfloat16(v.w);
    __nv_bfloat16 l0 = __float2bfloat16(v.x - __bfloat162float(h0));
    __nv_bfloat16 l1 = __float2bfloat16(v.y - __bfloat162float(h1));
    __nv_bfloat16 l2 = __float2bfloat16(v.z - __bfloat162float(h2));
    __nv_bfloat16 l3 = __float2bfloat16(v.w - __bfloat162float(h3));
    *(__nv_bfloat162*)(oh + off)     = __halves2bfloat162(h0, h1);
    *(__nv_bfloat162*)(oh + off + 2) = __halves2bfloat162(h2, h3);
    *(__nv_bfloat162*)(ol + off)     = __halves2bfloat162(l0, l1);
    *(__nv_bfloat162*)(ol + off + 2) = __halves2bfloat162(l2, l3);
}

__device__ __forceinline__ float block_reduce_sum_256(float v, float* red) {
    int t = threadIdx.x;
    red[t] = v;
    __syncthreads();
    #pragma unroll
    for (int s = 128; s > 0; s >>= 1) {
        if (t < s) red[t] += red[t + s];
        __syncthreads();
    }
    return red[0];
}

// ================= K0: rp, rc, vp hi/lo, uc hi/lo =================
__global__ void rv_kernel(const float* __restrict__ up, const float* __restrict__ uc,
                          const float* __restrict__ wa) {
    __shared__ float red[256];
    int row = blockIdx.x, t = threadIdx.x;
    if (row < M_) {
        const float* a = up + (size_t)row * D_;
        const float* w1 = wa;
        const float* w3 = wa + 2 * D_;
        float s = 0.f;
        for (int k = t * 4; k < D_; k += 1024) {
            float4 av = *(const float4*)(a + k);
            float4 w1v = *(const float4*)(w1 + k);
            float4 w3v = *(const float4*)(w3 + k);
            s += av.x * w1v.x + av.y * w1v.y + av.z * w1v.z + av.w * w1v.w;
            float4 vv = make_float4(av.x * w3v.x, av.y * w3v.y, av.z * w3v.z, av.w * w3v.w);
            split_store(g_vph, g_vpl, (size_t)row * D_ + k, vv);
        }
        float tot = block_reduce_sum_256(s, red);
        if (t == 0) g_rp[row] = tot;
    } else {
        int r2 = row - M_;
        const float* a = uc + (size_t)r2 * D_;
        const float* w2 = wa + D_;
        float s = 0.f;
        for (int k = t * 4; k < D_; k += 1024) {
            float4 av = *(const float4*)(a + k);
            float4 w2v = *(const float4*)(w2 + k);
            s += av.x * w2v.x + av.y * w2v.y + av.z * w2v.z + av.w * w2v.w;
            split_store(g_uch, g_ucl, (size_t)r2 * D_ + k, av);
        }
        float tot = block_reduce_sum_256(s, red);
        if (t == 0) g_rc[r2] = tot;
    }
}

// ================= transpose + split convert =================
__global__ void transpose_split(const float* __restrict__ in, int R, int C,
                                __nv_bfloat16* __restrict__ oh, __nv_bfloat16* __restrict__ ol) {
    __shared__ float t[32][33];
    int tx = threadIdx.x, ty = threadIdx.y;
    int r0 = blockIdx.y * 32, c0 = blockIdx.x * 32;
    #pragma unroll
    for (int j = 0; j < 4; j++)
        t[ty + j * 8][tx] = in[(size_t)(r0 + ty + j * 8) * C + c0 + tx];
    __syncthreads();
    #pragma unroll
    for (int j = 0; j < 4; j++) {
        int c = c0 + ty + j * 8;
        float v = t[tx][ty + j * 8];
        __nv_bfloat16 h = __float2bfloat16(v);
        __nv_bfloat16 l = __float2bfloat16(v - __bfloat162float(h));
        oh[(size_t)c * R + r0 + tx] = h;
        ol[(size_t)c * R + r0 + tx] = l;
    }
}

__global__ void transpose_softmax_split(const float* __restrict__ S) {
    __shared__ float t[32][33];
    int tx = threadIdx.x, ty = threadIdx.y;
    int r0 = blockIdx.y * 32, c0 = blockIdx.x * 32;
    float cm = g_cmax[c0 + tx], ci = g_cinv[c0 + tx];
    #pragma unroll
    for (int j = 0; j < 4; j++) {
        float v = S[(size_t)(r0 + ty + j * 8) * N_ + c0 + tx];
        t[ty + j * 8][tx] = __expf(v - cm) * ci;
    }
    __syncthreads();
    #pragma unroll
    for (int j = 0; j < 4; j++) {
        int c = c0 + ty + j * 8;
        float v = t[tx][ty + j * 8];
        __nv_bfloat16 h = __float2bfloat16(v);
        __nv_bfloat16 l = __float2bfloat16(v - __bfloat162float(h));
        g_SbTh[(size_t)c * M_ + r0 + tx] = h;
        g_SbTl[(size_t)c * M_ + r0 + tx] = l;
    }
}

// ================= col softmax stats =================
__global__ void col_stats_part(const float* __restrict__ S) {
    int tx = threadIdx.x, ty = threadIdx.y;
    int c = blockIdx.x * 128 + tx;
    int r0 = blockIdx.y * 128;
    float mx = -INFINITY, sm = 0.f;
    for (int r = ty; r < 128; r += 4) {
        float v = S[(size_t)(r0 + r) * N_ + c];
        float mn = fmaxf(mx, v);
        sm = sm * __expf(mx - mn) + __expf(v - mn);
        mx = mn;
    }
    __shared__ float m2[4][128], s2[4][128];
    m2[ty][tx] = mx; s2[ty][tx] = sm;
    __syncthreads();
    if (ty == 0) {
        float m = m2[0][tx], s = s2[0][tx];
        #pragma unroll
        for (int k = 1; k < 4; k++) {
            float mm = m2[k][tx], ss = s2[k][tx];
            float mn = fmaxf(m, mm);
            s = s * __expf(m - mn) + ss * __expf(mm - mn);
            m = mn;
        }
        g_pmax[blockIdx.y * N_ + c] = m;
        g_psum[blockIdx.y * N_ + c] = s;
    }
}

__global__ void col_stats_combine() {
    int c = blockIdx.x * 256 + threadIdx.x;
    float m = g_pmax[c], s = g_psum[c];
    #pragma unroll
    for (int k = 1; k < 8; k++) {
        float mm = g_pmax[k * N_ + c], ss = g_psum[k * N_ + c];
        float mn = fmaxf(m, mm);
        s = s * __expf(m - mn) + ss * __expf(mm - mn);
        m = mn;
    }
    g_cmax[c] = m;
    g_cinv[c] = 1.0f / s;
}

// ================= row softmax -> Sa hi/lo =================
__global__ void row_softmax_split(const float* __restrict__ S) {
    __shared__ float red[256];
    int row = blockIdx.x, t = threadIdx.x;
    float4 v = ((const float4*)(S + (size_t)row * N_))[t];
    float mx = fmaxf(fmaxf(v.x, v.y), fmaxf(v.z, v.w));
    red[t] = mx;
    __syncthreads();
    #pragma unroll
    for (int s = 128; s > 0; s >>= 1) {
        if (t < s) red[t] = fmaxf(red[t], red[t + s]);
        __syncthreads();
    }
    mx = red[0];
    __syncthreads();
    float e0 = __expf(v.x - mx), e1 = __expf(v.y - mx);
    float e2 = __expf(v.z - mx), e3 = __expf(v.w - mx);
    float sum = block_reduce_sum_256(e0 + e1 + e2 + e3, red);
    float inv = 1.0f / sum;
    split_store(g_Sah, g_Sal, (size_t)row * N_ + t * 4,
                make_float4(e0 * inv, e1 * inv, e2 * inv, e3 * inv));
}

// ================= merge split-K partials + rank-1 bias =================
__global__ void merge_S() {
    int row = blockIdx.x, t = threadIdx.x;
    float rpv = g_rp[row];
    int j = t * 4;
    float4 a = *(const float4*)(g_Sp + (size_t)row * N_ + j);
    float4 b = *(const float4*)(g_Sp + (size_t)M_ * N_ + (size_t)row * N_ + j);
    float4 c = *(const float4*)(g_Sp + 2 * (size_t)M_ * N_ + (size_t)row * N_ + j);
    float4 d = *(const float4*)(g_Sp + 3 * (size_t)M_ * N_ + (size_t)row * N_ + j);
    float4 rc4 = *(const float4*)(g_rc + j);
    float4 o;
    o.x = a.x + b.x + c.x + d.x + rpv + rc4.x;
    o.y = a.y + b.y + c.y + d.y + rpv + rc4.y;
    o.z = a.z + b.z + c.z + d.z + rpv + rc4.z;
    o.w = a.w + b.w + c.w + d.w + rpv + rc4.w;
    *(float4*)(g_S + (size_t)row * N_ + j) = o;
}

// ================= mma.sync GEMM core (bf16 hi/lo, 3 passes over K) =================
#define NSTG 2
#define TILE_B 16384
#define SMEM_GEMM (2 * NSTG * TILE_B)

__device__ __forceinline__ void cp_tile(uint32_t sdst, const __nv_bfloat16* src,
                                        int row0, int ld, int k0, int tid) {
    const char* gb = (const char*)(src + (size_t)row0 * ld + k0);
    size_t rb = (size_t)ld * 2;
    #pragma unroll
    for (int it = 0; it < 4; it++) {
        int idx = tid + it * 256;
        int r = idx >> 3;
        int cb = (idx & 7) << 4;
        const void* g = gb + (size_t)r * rb + cb;
        uint32_t s = sdst + SMEM_SWIZZLE_128B(r * 128 + cb);
        asm volatile("cp.async.cg.shared.global [%0], [%1], 16;" :: "r"(s), "l"(g));
    }
}

__device__ __forceinline__ void chunk_src(int ci, int nkc,
    const __nv_bfloat16* Ahi, const __nv_bfloat16* Alo,
    const __nv_bfloat16* Bhi, const __nv_bfloat16* Blo,
    const __nv_bfloat16** As, const __nv_bfloat16** Bs, int* kk)
{
    int p = ci / nkc;
    int kc = ci - p * nkc;
    *kk = kc << 6;
    *As = (p == 1) ? Alo : Ahi;
    *Bs = (p == 2) ? Blo : Bhi;
}

__device__ __forceinline__ void gemm_core(
    const __nv_bfloat16* __restrict__ Ahi, const __nv_bfloat16* __restrict__ Alo,
    const __nv_bfloat16* __restrict__ Bhi, const __nv_bfloat16* __restrict__ Blo,
    float* __restrict__ C, int ldc, int Kdim, int c0, int ncl, int i0, int j0)
{
    extern __shared__ __align__(1024) char smem[];
    uint32_t sb = smem_to_u32(smem);
    const int tid = threadIdx.x;
    const int wid = tid >> 5, lane = tid & 31;
    const int wm = wid & 1, wn = wid >> 1;      // warp tile 64x32 in 2x4 grid

    float acc[4][4][4];
    #pragma unroll
    for (int a = 0; a < 4; a++)
        #pragma unroll
        for (int b = 0; b < 4; b++)
            #pragma unroll
            for (int c = 0; c < 4; c++) acc[a][b][c] = 0.f;

    // per-thread ldmatrix offsets, swizzled once; k-step applied via XOR
    uint32_t cA = (uint32_t)((wm * 64 + (lane & 15)) << 7) + ((lane >> 4) << 4);
    cA ^= ((cA >> 3) & 0x70);
    uint32_t rowB = (lane & 7) + ((lane >> 4) << 3);
    uint32_t cB = (uint32_t)((wn * 32 + rowB) << 7) + (((lane >> 3) & 1) << 4);
    cB ^= ((cB >> 3) & 0x70);

    const int nkc = Kdim >> 6;

    #define STG_A(s) (sb + (s) * TILE_B)
    #define STG_B(s) (sb + NSTG * TILE_B + (s) * TILE_B)

    {
        const __nv_bfloat16 *As, *Bs; int kk;
        chunk_src(c0, nkc, Ahi, Alo, Bhi, Blo, &As, &Bs, &kk);
        cp_tile(STG_A(0), As, i0, Kdim, kk, tid);
        cp_tile(STG_B(0), Bs, j0, Kdim, kk, tid);
        asm volatile("cp.async.commit_group;" ::: "memory");
        chunk_src(c0 + 1, nkc, Ahi, Alo, Bhi, Blo, &As, &Bs, &kk);
        cp_tile(STG_A(1), As, i0, Kdim, kk, tid);
        cp_tile(STG_B(1), Bs, j0, Kdim, kk, tid);
        asm volatile("cp.async.commit_group;" ::: "memory");
    }

    for (int li = 0; li < ncl; li++) {
        int s = li & 1;
        asm volatile("cp.async.wait_group 1;" ::: "memory");
        __syncthreads();
        uint32_t aBase = STG_A(s) + cA;
        uint32_t bBase = STG_B(s) + cB;
        #pragma unroll
        for (int ks = 0; ks < 4; ks++) {
            uint32_t afr[4][4], bfr[2][4];
            #pragma unroll
            for (int mt = 0; mt < 4; mt++)
                LDSM_X4(afr[mt], (aBase + mt * 2048) ^ (ks << 5));
            #pragma unroll
            for (int p = 0; p < 2; p++)
                LDSM_X4(bfr[p], (bBase + p * 2048) ^ (ks << 5));
            #pragma unroll
            for (int mt = 0; mt < 4; mt++) {
                #pragma unroll
                for (int p = 0; p < 2; p++) {
                    mma16816(acc[mt][p * 2 + 0], afr[mt], bfr[p][0], bfr[p][1]);
                    mma16816(acc[mt][p * 2 + 1], afr[mt], bfr[p][2], bfr[p][3]);
                }
            }
        }
        __syncthreads();
        if (li + 2 < ncl) {
            const __nv_bfloat16 *As, *Bs; int kk;
            chunk_src(c0 + li + 2, nkc, Ahi, Alo, Bhi, Blo, &As, &Bs, &kk);
            cp_tile(STG_A(s), As, i0, Kdim, kk, tid);
            cp_tile(STG_B(s), Bs, j0, Kdim, kk, tid);
        }
        asm volatile("cp.async.commit_group;" ::: "memory");
    }

    const int gid = lane >> 2, tig = lane & 3;
    #pragma unroll
    for (int mt = 0; mt < 4; mt++) {
        int gi = i0 + wm * 64 + mt * 16 + gid;
        #pragma unroll
        for (int nt = 0; nt < 4; nt++) {
            int gj = j0 + wn * 32 + nt * 8 + tig * 2;
            *(float2*)(C + (size_t)gi * ldc + gj) = make_float2(acc[mt][nt][0], acc[mt][nt][1]);
            *(float2*)(C + (size_t)(gi + 8) * ldc + gj) = make_float2(acc[mt][nt][2], acc[mt][nt][3]);
        }
    }
    #undef STG_A
    #undef STG_B
}

// GEMM1: split-K x4, partial outputs
__global__ __launch_bounds__(256, 2) void gemm_splitk(
    const __nv_bfloat16* __restrict__ Ahi, const __nv_bfloat16* __restrict__ Alo,
    const __nv_bfloat16* __restrict__ Bhi, const __nv_bfloat16* __restrict__ Blo,
    float* __restrict__ Cp)
{
    int z = blockIdx.z;
    const int nch = 3 * (D_ >> 6);     // 96
    const int q = nch / 4;             // 24
    gemm_core(Ahi, Alo, Bhi, Blo, Cp + (size_t)z * M_ * N_, N_, D_,
              z * q, q, blockIdx.y * 128, blockIdx.x * 128);
}

// GEMM2+3 fused: z picks operand set
__global__ __launch_bounds__(256, 2) void gemm_dual(
    const __nv_bfloat16* __restrict__ A0h, const __nv_bfloat16* __restrict__ A0l,
    const __nv_bfloat16* __restrict__ B0h, const __nv_bfloat16* __restrict__ B0l,
    float* __restrict__ C0,
    const __nv_bfloat16* __restrict__ A1h, const __nv_bfloat16* __restrict__ A1l,
    const __nv_bfloat16* __restrict__ B1h, const __nv_bfloat16* __restrict__ B1l,
    float* __restrict__ C1)
{
    int z = blockIdx.z;
    const __nv_bfloat16* Ah = z ? A1h : A0h;
    const __nv_bfloat16* Al = z ? A1l : A0l;
    const __nv_bfloat16* Bh = z ? B1h : B0h;
    const __nv_bfloat16* Bl = z ? B1l : B0l;
    float* C = z ? C1 : C0;
    const int nch = 3 * (N_ >> 6);     // 48
    gemm_core(Ah, Al, Bh, Bl, C, D_, N_, 0, nch, blockIdx.y * 128, blockIdx.x * 128);
}

// ================= FFN =================
__global__ void ffn_partial(const float* __restrict__ up, const float* __restrict__ uc,
                            const float* __restrict__ W) {
    __shared__ float red[256];
    int i = blockIdx.x, t = threadIdx.x;
    const float* Wi = W + (size_t)i * 4 * D_;
    const float* upi = up + (size_t)i * D_;
    const float* uci = uc + (size_t)i * D_;
    const float* aai = g_aa + (size_t)i * D_;
    const float* abi = g_ab + (size_t)i * D_;
    float s = 0.f;
    for (int k = t * 4; k < D_; k += 1024) {
        float4 u  = *(const float4*)(upi + k);
        float4 aa = *(const float4*)(aai + k);
        float4 ab = *(const float4*)(abi + k);
        float4 cc = *(const float4*)(uci + k);
        float4 w0 = *(const float4*)(Wi + k);
        float4 w1 = *(const float4*)(Wi + D_ + k);
        float4 w2 = *(const float4*)(Wi + 2 * D_ + k);
        float4 w3 = *(const float4*)(Wi + 3 * D_ + k);
        s += u.x * w0.x + u.y * w0.y + u.z * w0.z + u.w * w0.w;
        s += aa.x * w1.x + aa.y * w1.y + aa.z * w1.z + aa.w * w1.w;
        s += u.x * aa.x * w2.x + u.y * aa.y * w2.y + u.z * aa.z * w2.z + u.w * aa.w * w2.w;
        s += cc.x * ab.x * w3.x + cc.y * ab.y * w3.y + cc.z * ab.z * w3.z + cc.w * ab.w * w3.w;
    }
    float tot = block_reduce_sum_256(s, red);
    if (t == 0) g_part[i] = tot;
}

__global__ void ffn_final(const float* __restrict__ b, float* __restrict__ out) {
    __shared__ float red[256];
    int t = threadIdx.x;
    float s = 0.f;
    for (int i = t; i < N_; i += 256) s += g_part[i];
    float tot = block_reduce_sum_256(s, red);
    if (t == 0) out[0] = fmaxf(tot + b[0], 0.f);
}

// ================= launch =================
extern "C" void kernel_launch(void* const* d_in, const int* in_sizes, int n_in,
                              void* d_out, int out_size) {
    const float* u_p   = (const float*)d_in[0];
    const float* u_c   = (const float*)d_in[1];
    const float* w_a   = (const float*)d_in[2];
    const float* ffn_w = (const float*)d_in[3];
    const float* ffn_b = (const float*)d_in[4];
    float* out = (float*)d_out;

    cudaFuncSetAttribute(gemm_splitk, cudaFuncAttributeMaxDynamicSharedMemorySize, SMEM_GEMM);
    cudaFuncSetAttribute(gemm_dual,   cudaFuncAttributeMaxDynamicSharedMemorySize, SMEM_GEMM);

    float *S, *Sp, *aa, *ab;
    __nv_bfloat16 *vph, *vpl, *uch, *ucl, *ucTh, *ucTl, *upTh, *upTl, *Sah, *Sal, *SbTh, *SbTl;
    cudaGetSymbolAddress((void**)&S, g_S);
    cudaGetSymbolAddress((void**)&Sp, g_Sp);
    cudaGetSymbolAddress((void**)&aa, g_aa);
    cudaGetSymbolAddress((void**)&ab, g_ab);
    cudaGetSymbolAddress((void**)&vph, g_vph);
    cudaGetSymbolAddress((void**)&vpl, g_vpl);
    cudaGetSymbolAddress((void**)&uch, g_uch);
    cudaGetSymbolAddress((void**)&ucl, g_ucl);
    cudaGetSymbolAddress((void**)&ucTh, g_ucTh);
    cudaGetSymbolAddress((void**)&ucTl, g_ucTl);
    cudaGetSymbolAddress((void**)&upTh, g_upTh);
    cudaGetSymbolAddress((void**)&upTl, g_upTl);
    cudaGetSymbolAddress((void**)&Sah, g_Sah);
    cudaGetSymbolAddress((void**)&Sal, g_Sal);
    cudaGetSymbolAddress((void**)&SbTh, g_SbTh);
    cudaGetSymbolAddress((void**)&SbTl, g_SbTl);

    // K0: rp, rc, vp hi/lo, uc hi/lo
    rv_kernel<<<M_ + N_, 256>>>(u_p, u_c, w_a);

    // transposed splits for GEMM2/3 B operands
    transpose_split<<<dim3(D_ / 32, N_ / 32), dim3(32, 8)>>>(u_c, N_, D_, ucTh, ucTl);
    transpose_split<<<dim3(D_ / 32, M_ / 32), dim3(32, 8)>>>(u_p, M_, D_, upTh, upTl);

    // GEMM1: S partials (split-K x4), then merge with rank-1 bias
    gemm_splitk<<<dim3(N_ / 128, M_ / 128, 4), 256, SMEM_GEMM>>>(vph, vpl, uch, ucl, Sp);
    merge_S<<<M_, 256>>>();

    // softmaxes
    row_softmax_split<<<M_, 256>>>(S);
    col_stats_part<<<dim3(N_ / 128, 8), dim3(128, 4)>>>(S);
    col_stats_combine<<<N_ / 256, 256>>>();
    transpose_softmax_split<<<dim3(N_ / 32, M_ / 32), dim3(32, 8)>>>(S);

    // GEMM2 + GEMM3 fused
    gemm_dual<<<dim3(D_ / 128, M_ / 128, 2), 256, SMEM_GEMM>>>(
        Sah, Sal, ucTh, ucTl, aa,
        SbTh, SbTl, upTh, upTl, ab);

    // FFN
    ffn_partial<<<N_, 256>>>(u_p, u_c, ffn_w);
    ffn_final<<<1, 256>>>(ffn_b, out);
}